// round 16
// baseline (speedup 1.0000x reference)
#include <cuda_runtime.h>
#include <cuda_fp16.h>
#include <math.h>
#include <stdint.h>

// Problem constants
#define BB   64
#define FF   32
#define NN   36
#define REGION 1024
#define HIDDEN 1024
#define FEAT2  3072
#define M1   (BB*FF*NN)       // 73728 rows of spatial GEMM
#define M2   (BB*FF)          // 2048 rows of temporal GEMM

// ---------------- scratch (device globals; no allocation allowed) ----------------
__device__ float  g_hproj_s[BB * 1024];
__device__ float  g_hproj_t[BB * 1024];
__device__ float  g_score1[M1];
__device__ float  g_feat[M2 * FEAT2];               // fp32 feat (output path)
__device__ float  g_score2[M2];
__device__ __half g_obj_h[(size_t)M1 * REGION];     // fp16 object_feats
__device__ __half g_feat_h[(size_t)M2 * FEAT2];     // fp16 feat (GEMM operand)
__device__ __half g_swv_h[1024 * REGION];           // fp16 s_wv_w
__device__ __half g_twv_h[1024 * FEAT2];            // fp16 t_wv_w
__device__ __half g_swh_h[1024 * HIDDEN];           // fp16 s_wh_w
__device__ __half g_twh_h[1024 * HIDDEN];           // fp16 t_wh_w
__device__ __half g_hid_h[128 * HIDDEN];            // fp16 hidden, padded to 128 rows

// ================= PTX helpers =================
__device__ __forceinline__ uint32_t smem_u32(const void* p) {
    uint32_t a;
    asm("{ .reg .u64 t; cvta.to.shared.u64 t, %1; cvt.u32.u64 %0, t; }" : "=r"(a) : "l"(p));
    return a;
}

__device__ __forceinline__ void cp_async16(uint32_t dst, const void* src) {
    asm volatile("cp.async.cg.shared.global [%0], [%1], 16;" :: "r"(dst), "l"(src));
}
#define CP_COMMIT() asm volatile("cp.async.commit_group;" ::: "memory")

__device__ __forceinline__ void ldsm_x4(uint32_t r[4], uint32_t addr) {
    asm volatile("ldmatrix.sync.aligned.m8n8.x4.shared.b16 {%0,%1,%2,%3}, [%4];"
                 : "=r"(r[0]), "=r"(r[1]), "=r"(r[2]), "=r"(r[3]) : "r"(addr));
}

__device__ __forceinline__ void mma_f16(float c[4], const uint32_t a[4], uint32_t b0, uint32_t b1) {
    asm volatile(
        "mma.sync.aligned.m16n8k16.row.col.f32.f16.f16.f32 "
        "{%0,%1,%2,%3}, {%4,%5,%6,%7}, {%8,%9}, {%0,%1,%2,%3};"
        : "+f"(c[0]), "+f"(c[1]), "+f"(c[2]), "+f"(c[3])
        : "r"(a[0]), "r"(a[1]), "r"(a[2]), "r"(a[3]), "r"(b0), "r"(b1));
}

__device__ __forceinline__ uint32_t h2_bits(__half2 h) {
    uint32_t u;
    memcpy(&u, &h, 4);
    return u;
}

// swizzled offset within a [rows x 64 half] tile (128B rows, SW128 pattern)
__device__ __forceinline__ uint32_t tile_off(int row, int chunk16) {
    return (uint32_t)(row * 128 + ((chunk16 ^ (row & 7)) << 4));
}

// ---- hoisted cp.async addressing: per-thread offsets computed once ----
template <int NT>
struct LoadCtx {
    uint32_t a_dst[2];
    uint32_t a_src[2];
    uint32_t w_dst[NT / 64];
    uint32_t w_src[NT / 64];
};

template <int NT>
__device__ __forceinline__ void ls_init(LoadCtx<NT>& ls, int K, int tid) {
    #pragma unroll
    for (int it = 0; it < 2; it++) {
        int id = tid + it * 512;
        int r = id >> 3, c = id & 7;
        ls.a_dst[it] = tile_off(r, c);
        ls.a_src[it] = (uint32_t)(r * K + c * 8);
    }
    #pragma unroll
    for (int it = 0; it < NT / 64; it++) {
        int id = tid + it * 512;
        int r = id >> 3, c = id & 7;
        ls.w_dst[it] = 16384u + tile_off(r, c);
        ls.w_src[it] = (uint32_t)(r * K + c * 8);
    }
}

template <int NT>
__device__ __forceinline__ void ls_issue(const LoadCtx<NT>& ls, uint32_t stage_base,
                                         const __half* Ag, const __half* Wg) {
    #pragma unroll
    for (int it = 0; it < 2; it++)
        cp_async16(stage_base + ls.a_dst[it], Ag + ls.a_src[it]);
    #pragma unroll
    for (int it = 0; it < NT / 64; it++)
        cp_async16(stage_base + ls.w_dst[it], Wg + ls.w_src[it]);
}

// one K-chunk (4 x k16) of MMAs from a stage buffer
#define GEMM_CHUNK(NI, stage_base)                                                    \
    _Pragma("unroll")                                                                 \
    for (int s = 0; s < 4; s++) {                                                     \
        const uint32_t x = (uint32_t)s << 5;                                          \
        uint32_t af[2][4];                                                            \
        _Pragma("unroll")                                                             \
        for (int mi = 0; mi < 2; mi++)                                                \
            ldsm_x4(af[mi], (stage_base) + (a_off[mi] ^ x));                          \
        uint32_t bf[NI][2];                                                           \
        _Pragma("unroll")                                                             \
        for (int p = 0; p < (NI) / 2; p++) {                                          \
            uint32_t r[4];                                                            \
            ldsm_x4(r, (stage_base) + (b_off[p] ^ x));                                \
            bf[2*p][0] = r[0]; bf[2*p][1] = r[2];                                     \
            bf[2*p+1][0] = r[1]; bf[2*p+1][1] = r[3];                                 \
        }                                                                             \
        _Pragma("unroll")                                                             \
        for (int mi = 0; mi < 2; mi++)                                                \
            _Pragma("unroll")                                                         \
            for (int ni = 0; ni < (NI); ni++)                                         \
                mma_f16(acc[mi][ni], af[mi], bf[ni][0], bf[ni][1]);                   \
    }

// ================= persistent spatial GEMM + tanh-dot epilogue =================
// Race-free pipeline: consume buffer, BARRIER, then refill it. wait_group 2 with
// 3 groups in flight; the refill target was consumed >=2 barriers earlier.
template <int NT, int NTX>
__global__ __launch_bounds__(512, 1) void gemm_score_pers(
    const __half* __restrict__ A, const __half* __restrict__ W,
    const float* __restrict__ hproj, const float* __restrict__ wa,
    float* __restrict__ score, int K, int rpb, int mb_per_cta)
{
    constexpr int WN = NT / 4;
    constexpr int NI = WN / 8;
    constexpr int STAGE = 16384 + NT * 128;
    constexpr int OFF_WA = 4 * STAGE;
    constexpr int OFF_HP = OFF_WA + NT * 4;
    constexpr int OFF_RED = OFF_HP + 4 * NT * 4;

    extern __shared__ char smem[];
    const uint32_t sb = smem_u32(smem);
    const int tid = threadIdx.x;
    const int lane = tid & 31;
    const int warp = tid >> 5;
    const int warp_m = warp >> 2;
    const int warp_n = warp & 3;
    const int G = gridDim.x;
    const int S = K >> 6;

    const int lrow = lane & 15;
    const int lhi  = lane >> 4;
    uint32_t a_off[2], b_off[NI / 2];
    #pragma unroll
    for (int mi = 0; mi < 2; mi++)
        a_off[mi] = tile_off(warp_m * 32 + mi * 16 + lrow, lhi);
    #pragma unroll
    for (int p = 0; p < NI / 2; p++)
        b_off[p] = 16384u + tile_off(warp_n * WN + p * 16 + lrow, lhi);

    LoadCtx<NT> ls;
    ls_init<NT>(ls, K, tid);

    const int chunks_total = mb_per_cta * NTX * S;
    int pf_kc = 0, pf_nx = 0, pf_mb = blockIdx.x;
    const __half* pfA = A + (size_t)pf_mb * 128 * K;
    const __half* pfW = W;
    int pf_count = 0;

    auto issue_pf = [&](int bufidx) {
        ls_issue<NT>(ls, sb + bufidx * STAGE, pfA + pf_kc * 64, pfW + pf_kc * 64);
        pf_count++;
        if (++pf_kc == S) {
            pf_kc = 0;
            if (++pf_nx == NTX) {
                pf_nx = 0; pf_mb += G;
                pfA = A + (size_t)pf_mb * 128 * K;
                pfW = W;
            } else {
                pfW += (size_t)NT * K;
            }
        }
    };

    // prologue: fill 3 of 4 stages
    #pragma unroll
    for (int q = 0; q < 3; q++) {
        if (pf_count < chunks_total) issue_pf(q);
        CP_COMMIT();
    }

    const int g = lane >> 2, tig = lane & 3;
    int ci = 0;

    for (int mbi = 0; mbi < mb_per_cta; mbi++) {
        const int m0 = (blockIdx.x + mbi * G) * 128;
        float sacc[2][2] = {{0.f, 0.f}, {0.f, 0.f}};

        for (int nx = 0; nx < NTX; nx++) {
            const int n0 = nx * NT;
            {
                float* wa_s = (float*)(smem + OFF_WA);
                float* hp_s = (float*)(smem + OFF_HP);
                for (int i = tid; i < NT; i += 512) wa_s[i] = wa[n0 + i];
                int nb = 128 / rpb; if (nb < 1) nb = 1;
                int b0 = m0 / rpb;
                for (int i = tid; i < nb * NT; i += 512)
                    hp_s[i] = hproj[(size_t)(b0 + i / NT) * 1024 + n0 + (i % NT)];
            }

            float acc[2][NI][4];
            #pragma unroll
            for (int i = 0; i < 2; i++)
                #pragma unroll
                for (int j = 0; j < NI; j++)
                    #pragma unroll
                    for (int q = 0; q < 4; q++) acc[i][j][q] = 0.f;

            for (int kc = 0; kc < S; kc++, ci++) {
                asm volatile("cp.async.wait_group 2;" ::: "memory");
                __syncthreads();
                const uint32_t stage_base = sb + (ci & 3) * STAGE;
                GEMM_CHUNK(NI, stage_base)
                __syncthreads();   // all warps done reading buffer (ci&3)
                if (pf_count < chunks_total) issue_pf((ci + 3) & 3);
                CP_COMMIT();
            }

            const float* wa_s = (const float*)(smem + OFF_WA);
            const float* hp_s = (const float*)(smem + OFF_HP);
            #pragma unroll
            for (int mi = 0; mi < 2; mi++) {
                int r0 = warp_m * 32 + mi * 16 + g;
                int r1 = r0 + 8;
                int bl0 = r0 / rpb, bl1 = r1 / rpb;
                const float* hp0 = hp_s + bl0 * NT;
                const float* hp1 = hp_s + bl1 * NT;
                float s0 = 0.f, s1 = 0.f;
                #pragma unroll
                for (int ni = 0; ni < NI; ni++) {
                    int cl = warp_n * WN + ni * 8 + 2 * tig;
                    float w0 = wa_s[cl], w1 = wa_s[cl + 1];
                    float t;
                    asm("tanh.approx.f32 %0, %1;" : "=f"(t) : "f"(acc[mi][ni][0] + hp0[cl]));     s0 += t * w0;
                    asm("tanh.approx.f32 %0, %1;" : "=f"(t) : "f"(acc[mi][ni][1] + hp0[cl + 1])); s0 += t * w1;
                    asm("tanh.approx.f32 %0, %1;" : "=f"(t) : "f"(acc[mi][ni][2] + hp1[cl]));     s1 += t * w0;
                    asm("tanh.approx.f32 %0, %1;" : "=f"(t) : "f"(acc[mi][ni][3] + hp1[cl + 1])); s1 += t * w1;
                }
                sacc[mi][0] += s0;
                sacc[mi][1] += s1;
            }
            __syncthreads();   // epilogue reads done before next tile's wa/hp writes
        }

        float* red = (float*)(smem + OFF_RED);
        #pragma unroll
        for (int mi = 0; mi < 2; mi++) {
            float s0 = sacc[mi][0], s1 = sacc[mi][1];
            s0 += __shfl_xor_sync(0xffffffffu, s0, 1);
            s0 += __shfl_xor_sync(0xffffffffu, s0, 2);
            s1 += __shfl_xor_sync(0xffffffffu, s1, 1);
            s1 += __shfl_xor_sync(0xffffffffu, s1, 2);
            if (tig == 0) {
                int r0 = warp_m * 32 + mi * 16 + g;
                red[warp_n * 128 + r0]     = s0;
                red[warp_n * 128 + r0 + 8] = s1;
            }
        }
        __syncthreads();
        for (int r = tid; r < 128; r += 512)
            score[m0 + r] = (red[r] + red[128 + r]) + (red[256 + r] + red[384 + r]);
        __syncthreads();
    }
}

// ================= GEMM + tanh-dot epilogue (temporal; atomics) ==========
template <int NT>
__global__ __launch_bounds__(512, 1) void gemm_score_mma(
    const __half* __restrict__ A, const __half* __restrict__ W,
    const float* __restrict__ hproj, const float* __restrict__ wa,
    float* __restrict__ score, int K, int rpb)
{
    constexpr int WN = NT / 4;
    constexpr int NI = WN / 8;
    constexpr int STAGE = 16384 + NT * 128;
    constexpr int OFF_WA = 4 * STAGE;
    constexpr int OFF_HP = OFF_WA + NT * 4;

    extern __shared__ char smem[];
    const uint32_t sb = smem_u32(smem);
    const int tid = threadIdx.x;
    const int lane = tid & 31;
    const int warp = tid >> 5;
    const int warp_m = warp >> 2;
    const int warp_n = warp & 3;
    const int m0 = blockIdx.y * 128;
    const int n0 = blockIdx.x * NT;
    const int S = K >> 6;

    {
        float* wa_s = (float*)(smem + OFF_WA);
        float* hp_s = (float*)(smem + OFF_HP);
        for (int i = tid; i < NT; i += 512) wa_s[i] = wa[n0 + i];
        int nb = 128 / rpb; if (nb < 1) nb = 1;
        int b0 = m0 / rpb;
        for (int i = tid; i < nb * NT; i += 512)
            hp_s[i] = hproj[(size_t)(b0 + i / NT) * 1024 + n0 + (i % NT)];
    }

    const __half* Abase = A + (size_t)m0 * K;
    const __half* Wbase = W + (size_t)n0 * K;

    float acc[2][NI][4];
    #pragma unroll
    for (int i = 0; i < 2; i++)
        #pragma unroll
        for (int j = 0; j < NI; j++)
            #pragma unroll
            for (int q = 0; q < 4; q++) acc[i][j][q] = 0.f;

    const int lrow = lane & 15;
    const int lhi  = lane >> 4;
    uint32_t a_off[2], b_off[NI / 2];
    #pragma unroll
    for (int mi = 0; mi < 2; mi++)
        a_off[mi] = tile_off(warp_m * 32 + mi * 16 + lrow, lhi);
    #pragma unroll
    for (int p = 0; p < NI / 2; p++)
        b_off[p] = 16384u + tile_off(warp_n * WN + p * 16 + lrow, lhi);

    LoadCtx<NT> ls;
    ls_init<NT>(ls, K, tid);

    ls_issue<NT>(ls, sb + 0 * STAGE, Abase +   0, Wbase +   0); CP_COMMIT();
    ls_issue<NT>(ls, sb + 1 * STAGE, Abase +  64, Wbase +  64); CP_COMMIT();
    ls_issue<NT>(ls, sb + 2 * STAGE, Abase + 128, Wbase + 128); CP_COMMIT();

    for (int kc = 0; kc < S; kc++) {
        asm volatile("cp.async.wait_group 2;" ::: "memory");
        __syncthreads();
        const uint32_t stage_base = sb + (kc & 3) * STAGE;
        GEMM_CHUNK(NI, stage_base)
        __syncthreads();
        if (kc + 3 < S)
            ls_issue<NT>(ls, sb + ((kc + 3) & 3) * STAGE,
                         Abase + (kc + 3) * 64, Wbase + (kc + 3) * 64);
        CP_COMMIT();
    }

    const float* wa_s = (const float*)(smem + OFF_WA);
    const float* hp_s = (const float*)(smem + OFF_HP);
    const int g = lane >> 2, tig = lane & 3;

    #pragma unroll
    for (int mi = 0; mi < 2; mi++) {
        int r0 = warp_m * 32 + mi * 16 + g;
        int r1 = r0 + 8;
        int bl0 = r0 / rpb, bl1 = r1 / rpb;
        const float* hp0 = hp_s + bl0 * NT;
        const float* hp1 = hp_s + bl1 * NT;
        float s0 = 0.f, s1 = 0.f;
        #pragma unroll
        for (int ni = 0; ni < NI; ni++) {
            int cl = warp_n * WN + ni * 8 + 2 * tig;
            float w0 = wa_s[cl], w1 = wa_s[cl + 1];
            float t;
            asm("tanh.approx.f32 %0, %1;" : "=f"(t) : "f"(acc[mi][ni][0] + hp0[cl]));     s0 += t * w0;
            asm("tanh.approx.f32 %0, %1;" : "=f"(t) : "f"(acc[mi][ni][1] + hp0[cl + 1])); s0 += t * w1;
            asm("tanh.approx.f32 %0, %1;" : "=f"(t) : "f"(acc[mi][ni][2] + hp1[cl]));     s1 += t * w0;
            asm("tanh.approx.f32 %0, %1;" : "=f"(t) : "f"(acc[mi][ni][3] + hp1[cl + 1])); s1 += t * w1;
        }
        s0 += __shfl_xor_sync(0xffffffffu, s0, 1);
        s0 += __shfl_xor_sync(0xffffffffu, s0, 2);
        s1 += __shfl_xor_sync(0xffffffffu, s1, 1);
        s1 += __shfl_xor_sync(0xffffffffu, s1, 2);
        if (tig == 0) {
            atomicAdd(&score[m0 + r0], s0);
            atomicAdd(&score[m0 + r1], s1);
        }
    }
}

// ================= GEMM + bias store (hproj) =================
__global__ __launch_bounds__(512, 1) void gemm_bias_mma(
    const __half* __restrict__ A,
    const __half* __restrict__ Ws, const float* __restrict__ bh_s,
    const float* __restrict__ bv_s, float* __restrict__ out_s,
    const __half* __restrict__ Wt, const float* __restrict__ bh_t,
    const float* __restrict__ bv_t, float* __restrict__ out_t)
{
    constexpr int NT = 256, WN = 64, NI = 8, K = HIDDEN;
    constexpr int STAGE = 16384 + NT * 128;
    constexpr int OFF_B = 4 * STAGE;

    extern __shared__ char smem[];
    const uint32_t sb = smem_u32(smem);
    const int tid = threadIdx.x;
    const int lane = tid & 31;
    const int warp = tid >> 5;
    const int warp_m = warp >> 2;
    const int warp_n = warp & 3;
    const int mat = blockIdx.y >> 2;
    const int n0 = (blockIdx.y & 3) * NT;
    const __half* W = mat ? Wt : Ws;
    const float* bh = mat ? bh_t : bh_s;
    const float* bv = mat ? bv_t : bv_s;
    float* out = mat ? out_t : out_s;

    {
        float* b_s = (float*)(smem + OFF_B);
        for (int i = tid; i < NT; i += 512) b_s[i] = bh[n0 + i] + bv[n0 + i];
    }

    const __half* Abase = A;
    const __half* Wbase = W + (size_t)n0 * K;

    float acc[2][NI][4];
    #pragma unroll
    for (int i = 0; i < 2; i++)
        #pragma unroll
        for (int j = 0; j < NI; j++)
            #pragma unroll
            for (int q = 0; q < 4; q++) acc[i][j][q] = 0.f;

    const int lrow = lane & 15;
    const int lhi  = lane >> 4;
    uint32_t a_off[2], b_off[NI / 2];
    #pragma unroll
    for (int mi = 0; mi < 2; mi++)
        a_off[mi] = tile_off(warp_m * 32 + mi * 16 + lrow, lhi);
    #pragma unroll
    for (int p = 0; p < NI / 2; p++)
        b_off[p] = 16384u + tile_off(warp_n * WN + p * 16 + lrow, lhi);

    LoadCtx<NT> ls;
    ls_init<NT>(ls, K, tid);

    ls_issue<NT>(ls, sb + 0 * STAGE, Abase +   0, Wbase +   0); CP_COMMIT();
    ls_issue<NT>(ls, sb + 1 * STAGE, Abase +  64, Wbase +  64); CP_COMMIT();
    ls_issue<NT>(ls, sb + 2 * STAGE, Abase + 128, Wbase + 128); CP_COMMIT();

    for (int kc = 0; kc < (K >> 6); kc++) {
        asm volatile("cp.async.wait_group 2;" ::: "memory");
        __syncthreads();
        const uint32_t stage_base = sb + (kc & 3) * STAGE;
        GEMM_CHUNK(NI, stage_base)
        __syncthreads();
        if (kc + 3 < (K >> 6))
            ls_issue<NT>(ls, sb + ((kc + 3) & 3) * STAGE,
                         Abase + (kc + 3) * 64, Wbase + (kc + 3) * 64);
        CP_COMMIT();
    }

    const float* b_s = (const float*)(smem + OFF_B);
    const int g = lane >> 2, tig = lane & 3;
    #pragma unroll
    for (int mi = 0; mi < 2; mi++) {
        int r0 = warp_m * 32 + mi * 16 + g;
        int r1 = r0 + 8;
        #pragma unroll
        for (int ni = 0; ni < NI; ni++) {
            int cl = warp_n * WN + ni * 8 + 2 * tig;
            if (r0 < 64) {
                out[r0 * 1024 + n0 + cl]     = acc[mi][ni][0] + b_s[cl];
                out[r0 * 1024 + n0 + cl + 1] = acc[mi][ni][1] + b_s[cl + 1];
            }
            if (r1 < 64) {
                out[r1 * 1024 + n0 + cl]     = acc[mi][ni][2] + b_s[cl];
                out[r1 * 1024 + n0 + cl + 1] = acc[mi][ni][3] + b_s[cl + 1];
            }
        }
    }
}

// ================= small kernels =================
__global__ void zero_kernel(float* __restrict__ p, int n) {
    int i = blockIdx.x * blockDim.x + threadIdx.x;
    if (i < n) p[i] = 0.0f;
}

// f32 -> f16, 8 elements per thread (2x LDG.128 + 1x STG.128), n % 8 == 0
__global__ __launch_bounds__(256) void cvt_f2h8(const float* __restrict__ in,
                                                __half* __restrict__ out, int n) {
    int i = (blockIdx.x * blockDim.x + threadIdx.x) * 8;
    if (i < n) {
        float4 v0 = *(const float4*)(in + i);
        float4 v1 = *(const float4*)(in + i + 4);
        uint4 o;
        o.x = h2_bits(__floats2half2_rn(v0.x, v0.y));
        o.y = h2_bits(__floats2half2_rn(v0.z, v0.w));
        o.z = h2_bits(__floats2half2_rn(v1.x, v1.y));
        o.w = h2_bits(__floats2half2_rn(v1.z, v1.w));
        *(uint4*)(out + i) = o;
    }
}

// hidden [64,1024] f32 -> [128,1024] f16 (rows 64..127 zero)
__global__ __launch_bounds__(256) void cvt_hid_pad(const float* __restrict__ in,
                                                   __half* __restrict__ out) {
    int i = (blockIdx.x * blockDim.x + threadIdx.x) * 4;
    if (i < 128 * HIDDEN) {
        __half2* o = (__half2*)(out + i);
        if (i < 64 * HIDDEN) {
            float4 v = *(const float4*)(in + i);
            o[0] = __floats2half2_rn(v.x, v.y);
            o[1] = __floats2half2_rn(v.z, v.w);
        } else {
            o[0] = __floats2half2_rn(0.f, 0.f);
            o[1] = __floats2half2_rn(0.f, 0.f);
        }
    }
}

// spatial softmax + weighted object sum + concat (fp32 + fp16 outputs)
__global__ __launch_bounds__(256) void spatial_kernel(
    const __half* __restrict__ obj_h, const float* __restrict__ frame,
    const float* __restrict__ score, float* __restrict__ feat,
    __half* __restrict__ feat_h)
{
    int bf = blockIdx.x;
    __shared__ float alpha[NN];
    if (threadIdx.x == 0) {
        float s[NN];
        float mx = -1e30f;
        #pragma unroll
        for (int n = 0; n < NN; n++) { s[n] = score[bf * NN + n]; mx = fmaxf(mx, s[n]); }
        float sum = 0.f;
        #pragma unroll
        for (int n = 0; n < NN; n++) { float e = expf(s[n] - mx); alpha[n] = e; sum += e; }
        float inv = 1.f / sum;
        #pragma unroll
        for (int n = 0; n < NN; n++) alpha[n] *= inv;
    }
    __syncthreads();

    const uint4* base4 = (const uint4*)(obj_h + (size_t)bf * NN * REGION);
    float* frow = feat + (size_t)bf * FEAT2;
    uint4* hrow4 = (uint4*)(feat_h + (size_t)bf * FEAT2);
    for (int d8 = threadIdx.x; d8 < REGION / 8; d8 += 256) {
        float a[8] = {0, 0, 0, 0, 0, 0, 0, 0};
        #pragma unroll 4
        for (int n = 0; n < NN; n++) {
            uint4 v = base4[n * (REGION / 8) + d8];
            float al = alpha[n];
            float2 p0 = __half22float2(*(__half2*)&v.x);
            float2 p1 = __half22float2(*(__half2*)&v.y);
            float2 p2 = __half22float2(*(__half2*)&v.z);
            float2 p3 = __half22float2(*(__half2*)&v.w);
            a[0] += al * p0.x; a[1] += al * p0.y;
            a[2] += al * p1.x; a[3] += al * p1.y;
            a[4] += al * p2.x; a[5] += al * p2.y;
            a[6] += al * p3.x; a[7] += al * p3.y;
        }
        #pragma unroll
        for (int q = 0; q < 8; q++) frow[d8 * 8 + q] = a[q];
        uint4 o;
        o.x = h2_bits(__floats2half2_rn(a[0], a[1]));
        o.y = h2_bits(__floats2half2_rn(a[2], a[3]));
        o.z = h2_bits(__floats2half2_rn(a[4], a[5]));
        o.w = h2_bits(__floats2half2_rn(a[6], a[7]));
        hrow4[d8] = o;
    }
    const float* frm = frame + (size_t)bf * (2 * HIDDEN);
    for (int d = threadIdx.x; d < 2 * HIDDEN; d += 256) {
        float v = frm[d];
        frow[REGION + d] = v;
        feat_h[(size_t)bf * FEAT2 + REGION + d] = __float2half_rn(v);
    }
}

// temporal softmax + weighted sum, fp32 feat -> fp32 output
__global__ __launch_bounds__(256) void temporal_kernel(
    const float* __restrict__ feat, const float* __restrict__ score2,
    float* __restrict__ out)
{
    int b = blockIdx.x;
    __shared__ float beta[FF];
    if (threadIdx.x == 0) {
        float s[FF];
        float mx = -1e30f;
        #pragma unroll
        for (int f = 0; f < FF; f++) { s[f] = score2[b * FF + f]; mx = fmaxf(mx, s[f]); }
        float sum = 0.f;
        #pragma unroll
        for (int f = 0; f < FF; f++) { float e = expf(s[f] - mx); beta[f] = e; sum += e; }
        float inv = 1.f / sum;
        #pragma unroll
        for (int f = 0; f < FF; f++) beta[f] *= inv;
    }
    __syncthreads();

    int d0 = blockIdx.y * (FEAT2 / 4);
    for (int d = d0 + threadIdx.x; d < d0 + FEAT2 / 4; d += 256) {
        float acc = 0.f;
        #pragma unroll 8
        for (int f = 0; f < FF; f++)
            acc += beta[f] * feat[((size_t)b * FF + f) * FEAT2 + d];
        out[(size_t)b * FEAT2 + d] = acc;
    }
}

// ================= launch =================
extern "C" void kernel_launch(void* const* d_in, const int* in_sizes, int n_in,
                              void* d_out, int out_size)
{
    const float* frame  = (const float*)d_in[0];
    const float* obj    = (const float*)d_in[1];
    const float* hidden = (const float*)d_in[2];
    const float* s_wh_w = (const float*)d_in[3];
    const float* s_wh_b = (const float*)d_in[4];
    const float* s_wv_w = (const float*)d_in[5];
    const float* s_wv_b = (const float*)d_in[6];
    const float* s_wa_w = (const float*)d_in[7];
    const float* t_wh_w = (const float*)d_in[8];
    const float* t_wh_b = (const float*)d_in[9];
    const float* t_wv_w = (const float*)d_in[10];
    const float* t_wv_b = (const float*)d_in[11];
    const float* t_wa_w = (const float*)d_in[12];
    float* out = (float*)d_out;

    float *p_hs, *p_ht, *p_s1, *p_feat, *p_s2;
    __half *p_obj_h, *p_feat_h, *p_swv_h, *p_twv_h, *p_swh_h, *p_twh_h, *p_hid_h;
    cudaGetSymbolAddress((void**)&p_hs, g_hproj_s);
    cudaGetSymbolAddress((void**)&p_ht, g_hproj_t);
    cudaGetSymbolAddress((void**)&p_s1, g_score1);
    cudaGetSymbolAddress((void**)&p_feat, g_feat);
    cudaGetSymbolAddress((void**)&p_s2, g_score2);
    cudaGetSymbolAddress((void**)&p_obj_h, g_obj_h);
    cudaGetSymbolAddress((void**)&p_feat_h, g_feat_h);
    cudaGetSymbolAddress((void**)&p_swv_h, g_swv_h);
    cudaGetSymbolAddress((void**)&p_twv_h, g_twv_h);
    cudaGetSymbolAddress((void**)&p_swh_h, g_swh_h);
    cudaGetSymbolAddress((void**)&p_twh_h, g_twh_h);
    cudaGetSymbolAddress((void**)&p_hid_h, g_hid_h);

    const int SMEM_PERS = 4 * (16384 + 256 * 128) + 256 * 4 + 4 * 256 * 4 + 4 * 128 * 4; // 203776
    const int SMEM_128  = 4 * (16384 + 128 * 128) + 128 * 4 + 4 * 128 * 4;               // 133632
    const int SMEM_B    = 4 * (16384 + 256 * 128) + 256 * 4;                             // 197632
    cudaFuncSetAttribute(gemm_score_pers<256, 4>, cudaFuncAttributeMaxDynamicSharedMemorySize, SMEM_PERS);
    cudaFuncSetAttribute(gemm_score_mma<128>, cudaFuncAttributeMaxDynamicSharedMemorySize, SMEM_128);
    cudaFuncSetAttribute(gemm_bias_mma, cudaFuncAttributeMaxDynamicSharedMemorySize, SMEM_B);

    // fp16 conversions (8 elems/thread)
    {
        int n_swh = 1024 * HIDDEN;
        cvt_f2h8<<<(n_swh / 8 + 255) / 256, 256>>>(s_wh_w, p_swh_h, n_swh);
        cvt_f2h8<<<(n_swh / 8 + 255) / 256, 256>>>(t_wh_w, p_twh_h, n_swh);
        cvt_hid_pad<<<(128 * HIDDEN / 4 + 255) / 256, 256>>>(hidden, p_hid_h);
        int n_swv = 1024 * REGION;
        cvt_f2h8<<<(n_swv / 8 + 255) / 256, 256>>>(s_wv_w, p_swv_h, n_swv);
        int n_twv = 1024 * FEAT2;
        cvt_f2h8<<<(n_twv / 8 + 255) / 256, 256>>>(t_wv_w, p_twv_h, n_twv);
        int n_obj = M1 * REGION;
        cvt_f2h8<<<(n_obj / 8 + 255) / 256, 256>>>(obj, p_obj_h, n_obj);
    }

    // hidden-state projections as one mma GEMM launch (both matrices)
    gemm_bias_mma<<<dim3(1, 8), 512, SMEM_B>>>(p_hid_h,
                                               p_swh_h, s_wh_b, s_wv_b, p_hs,
                                               p_twh_h, t_wh_b, t_wv_b, p_ht);

    // spatial attention scores: persistent GEMM, 144 CTAs x 4 m-blocks x 4 n-tiles
    gemm_score_pers<256, 4><<<144, 512, SMEM_PERS>>>(
        p_obj_h, p_swv_h, p_hs, s_wa_w, p_s1, REGION, FF * NN, (M1 / 128) / 144);

    // softmax over boxes + weighted object sum + concat (fp32 + fp16 feat)
    spatial_kernel<<<M2, 256>>>(p_obj_h, frame, p_s1, p_feat, p_feat_h);

    // temporal attention scores
    zero_kernel<<<(M2 + 255) / 256, 256>>>(p_s2, M2);
    gemm_score_mma<128><<<dim3(8, M2 / 128), 512, SMEM_128>>>(
        p_feat_h, p_twv_h, p_ht, t_wa_w, p_s2, FEAT2, FF);

    // softmax over frames + weighted feat sum (fp32) -> [64, 3072]
    temporal_kernel<<<dim3(BB, 4), 256>>>(p_feat, p_s2, out);
}

// round 17
// speedup vs baseline: 1.0604x; 1.0604x over previous
#include <cuda_runtime.h>
#include <cuda_fp16.h>
#include <math.h>
#include <stdint.h>

// Problem constants
#define BB   64
#define FF   32
#define NN   36
#define REGION 1024
#define HIDDEN 1024
#define FEAT2  3072
#define M1   (BB*FF*NN)       // 73728 rows of spatial GEMM
#define M2   (BB*FF)          // 2048 rows of temporal GEMM

// ---------------- scratch (device globals; no allocation allowed) ----------------
__device__ float  g_hproj_s[BB * 1024];
__device__ float  g_hproj_t[BB * 1024];
__device__ float  g_score1[M1];
__device__ float  g_feat[M2 * FEAT2];               // fp32 feat (output path)
__device__ float  g_score2[M2];
__device__ __half g_obj_h[(size_t)M1 * REGION];     // fp16 object_feats
__device__ __half g_feat_h[(size_t)M2 * FEAT2];     // fp16 feat (GEMM operand)
__device__ __half g_swv_h[1024 * REGION];           // fp16 s_wv_w
__device__ __half g_twv_h[1024 * FEAT2];            // fp16 t_wv_w
__device__ __half g_swh_h[1024 * HIDDEN];           // fp16 s_wh_w
__device__ __half g_twh_h[1024 * HIDDEN];           // fp16 t_wh_w
__device__ __half g_hid_h[128 * HIDDEN];            // fp16 hidden, padded to 128 rows

// ================= PTX helpers =================
__device__ __forceinline__ uint32_t smem_u32(const void* p) {
    uint32_t a;
    asm("{ .reg .u64 t; cvta.to.shared.u64 t, %1; cvt.u32.u64 %0, t; }" : "=r"(a) : "l"(p));
    return a;
}

__device__ __forceinline__ void cp_async16(uint32_t dst, const void* src) {
    asm volatile("cp.async.cg.shared.global [%0], [%1], 16;" :: "r"(dst), "l"(src));
}
#define CP_COMMIT() asm volatile("cp.async.commit_group;" ::: "memory")

__device__ __forceinline__ void ldsm_x4(uint32_t r[4], uint32_t addr) {
    asm volatile("ldmatrix.sync.aligned.m8n8.x4.shared.b16 {%0,%1,%2,%3}, [%4];"
                 : "=r"(r[0]), "=r"(r[1]), "=r"(r[2]), "=r"(r[3]) : "r"(addr));
}

__device__ __forceinline__ void mma_f16(float c[4], const uint32_t a[4], uint32_t b0, uint32_t b1) {
    asm volatile(
        "mma.sync.aligned.m16n8k16.row.col.f32.f16.f16.f32 "
        "{%0,%1,%2,%3}, {%4,%5,%6,%7}, {%8,%9}, {%0,%1,%2,%3};"
        : "+f"(c[0]), "+f"(c[1]), "+f"(c[2]), "+f"(c[3])
        : "r"(a[0]), "r"(a[1]), "r"(a[2]), "r"(a[3]), "r"(b0), "r"(b1));
}

__device__ __forceinline__ uint32_t h2_bits(__half2 h) {
    uint32_t u;
    memcpy(&u, &h, 4);
    return u;
}

// swizzled offset within a [rows x 64 half] tile (128B rows, SW128 pattern)
__device__ __forceinline__ uint32_t tile_off(int row, int chunk16) {
    return (uint32_t)(row * 128 + ((chunk16 ^ (row & 7)) << 4));
}

// ---- hoisted cp.async addressing: per-thread offsets computed once ----
template <int NT>
struct LoadCtx {
    uint32_t a_dst[2];
    uint32_t a_src[2];
    uint32_t w_dst[NT / 64];
    uint32_t w_src[NT / 64];
};

template <int NT>
__device__ __forceinline__ void ls_init(LoadCtx<NT>& ls, int K, int tid) {
    #pragma unroll
    for (int it = 0; it < 2; it++) {
        int id = tid + it * 512;
        int r = id >> 3, c = id & 7;
        ls.a_dst[it] = tile_off(r, c);
        ls.a_src[it] = (uint32_t)(r * K + c * 8);
    }
    #pragma unroll
    for (int it = 0; it < NT / 64; it++) {
        int id = tid + it * 512;
        int r = id >> 3, c = id & 7;
        ls.w_dst[it] = 16384u + tile_off(r, c);
        ls.w_src[it] = (uint32_t)(r * K + c * 8);
    }
}

template <int NT>
__device__ __forceinline__ void ls_issue(const LoadCtx<NT>& ls, uint32_t stage_base,
                                         const __half* Ag, const __half* Wg) {
    #pragma unroll
    for (int it = 0; it < 2; it++)
        cp_async16(stage_base + ls.a_dst[it], Ag + ls.a_src[it]);
    #pragma unroll
    for (int it = 0; it < NT / 64; it++)
        cp_async16(stage_base + ls.w_dst[it], Wg + ls.w_src[it]);
}

// one K-chunk (4 x k16) of MMAs from a stage buffer
#define GEMM_CHUNK(NI, stage_base)                                                    \
    _Pragma("unroll")                                                                 \
    for (int s = 0; s < 4; s++) {                                                     \
        const uint32_t x = (uint32_t)s << 5;                                          \
        uint32_t af[2][4];                                                            \
        _Pragma("unroll")                                                             \
        for (int mi = 0; mi < 2; mi++)                                                \
            ldsm_x4(af[mi], (stage_base) + (a_off[mi] ^ x));                          \
        uint32_t bf[NI][2];                                                           \
        _Pragma("unroll")                                                             \
        for (int p = 0; p < (NI) / 2; p++) {                                          \
            uint32_t r[4];                                                            \
            ldsm_x4(r, (stage_base) + (b_off[p] ^ x));                                \
            bf[2*p][0] = r[0]; bf[2*p][1] = r[2];                                     \
            bf[2*p+1][0] = r[1]; bf[2*p+1][1] = r[3];                                 \
        }                                                                             \
        _Pragma("unroll")                                                             \
        for (int mi = 0; mi < 2; mi++)                                                \
            _Pragma("unroll")                                                         \
            for (int ni = 0; ni < (NI); ni++)                                         \
                mma_f16(acc[mi][ni], af[mi], bf[ni][0], bf[ni][1]);                   \
    }

// ================= persistent spatial GEMM + tanh-dot epilogue =================
// Race-free single-sync pipeline:
//   wait_group 2 -> sync -> issue into (ci+3)&3 -> commit -> consume (ci&3)
// The refill target (ci-1)&3 was read at iteration ci-1; all those reads
// happen-before this iteration's __syncthreads, which precedes the write.
template <int NT, int NTX>
__global__ __launch_bounds__(512, 1) void gemm_score_pers(
    const __half* __restrict__ A, const __half* __restrict__ W,
    const float* __restrict__ hproj, const float* __restrict__ wa,
    float* __restrict__ score, int K, int rpb, int mb_per_cta)
{
    constexpr int WN = NT / 4;
    constexpr int NI = WN / 8;
    constexpr int STAGE = 16384 + NT * 128;
    constexpr int OFF_WA = 4 * STAGE;
    constexpr int OFF_HP = OFF_WA + NT * 4;
    constexpr int OFF_RED = OFF_HP + 4 * NT * 4;

    extern __shared__ char smem[];
    const uint32_t sb = smem_u32(smem);
    const int tid = threadIdx.x;
    const int lane = tid & 31;
    const int warp = tid >> 5;
    const int warp_m = warp >> 2;
    const int warp_n = warp & 3;
    const int G = gridDim.x;
    const int S = K >> 6;

    const int lrow = lane & 15;
    const int lhi  = lane >> 4;
    uint32_t a_off[2], b_off[NI / 2];
    #pragma unroll
    for (int mi = 0; mi < 2; mi++)
        a_off[mi] = tile_off(warp_m * 32 + mi * 16 + lrow, lhi);
    #pragma unroll
    for (int p = 0; p < NI / 2; p++)
        b_off[p] = 16384u + tile_off(warp_n * WN + p * 16 + lrow, lhi);

    LoadCtx<NT> ls;
    ls_init<NT>(ls, K, tid);

    const int chunks_total = mb_per_cta * NTX * S;
    int pf_kc = 0, pf_nx = 0, pf_mb = blockIdx.x;
    const __half* pfA = A + (size_t)pf_mb * 128 * K;
    const __half* pfW = W;
    int pf_count = 0;

    auto issue_pf = [&](int bufidx) {
        ls_issue<NT>(ls, sb + bufidx * STAGE, pfA + pf_kc * 64, pfW + pf_kc * 64);
        pf_count++;
        if (++pf_kc == S) {
            pf_kc = 0;
            if (++pf_nx == NTX) {
                pf_nx = 0; pf_mb += G;
                pfA = A + (size_t)pf_mb * 128 * K;
                pfW = W;
            } else {
                pfW += (size_t)NT * K;
            }
        }
    };

    // prologue: fill 3 of 4 stages
    #pragma unroll
    for (int q = 0; q < 3; q++) {
        if (pf_count < chunks_total) issue_pf(q);
        CP_COMMIT();
    }

    const int g = lane >> 2, tig = lane & 3;
    int ci = 0;

    for (int mbi = 0; mbi < mb_per_cta; mbi++) {
        const int m0 = (blockIdx.x + mbi * G) * 128;
        float sacc[2][2] = {{0.f, 0.f}, {0.f, 0.f}};

        for (int nx = 0; nx < NTX; nx++) {
            const int n0 = nx * NT;
            {
                float* wa_s = (float*)(smem + OFF_WA);
                float* hp_s = (float*)(smem + OFF_HP);
                for (int i = tid; i < NT; i += 512) wa_s[i] = wa[n0 + i];
                int nb = 128 / rpb; if (nb < 1) nb = 1;
                int b0 = m0 / rpb;
                for (int i = tid; i < nb * NT; i += 512)
                    hp_s[i] = hproj[(size_t)(b0 + i / NT) * 1024 + n0 + (i % NT)];
            }

            float acc[2][NI][4];
            #pragma unroll
            for (int i = 0; i < 2; i++)
                #pragma unroll
                for (int j = 0; j < NI; j++)
                    #pragma unroll
                    for (int q = 0; q < 4; q++) acc[i][j][q] = 0.f;

            for (int kc = 0; kc < S; kc++, ci++) {
                asm volatile("cp.async.wait_group 2;" ::: "memory");
                __syncthreads();
                if (pf_count < chunks_total) issue_pf((ci + 3) & 3);
                CP_COMMIT();
                const uint32_t stage_base = sb + (ci & 3) * STAGE;
                GEMM_CHUNK(NI, stage_base)
            }

            const float* wa_s = (const float*)(smem + OFF_WA);
            const float* hp_s = (const float*)(smem + OFF_HP);
            #pragma unroll
            for (int mi = 0; mi < 2; mi++) {
                int r0 = warp_m * 32 + mi * 16 + g;
                int r1 = r0 + 8;
                int bl0 = r0 / rpb, bl1 = r1 / rpb;
                const float* hp0 = hp_s + bl0 * NT;
                const float* hp1 = hp_s + bl1 * NT;
                float s0 = 0.f, s1 = 0.f;
                #pragma unroll
                for (int ni = 0; ni < NI; ni++) {
                    int cl = warp_n * WN + ni * 8 + 2 * tig;
                    float w0 = wa_s[cl], w1 = wa_s[cl + 1];
                    float t;
                    asm("tanh.approx.f32 %0, %1;" : "=f"(t) : "f"(acc[mi][ni][0] + hp0[cl]));     s0 += t * w0;
                    asm("tanh.approx.f32 %0, %1;" : "=f"(t) : "f"(acc[mi][ni][1] + hp0[cl + 1])); s0 += t * w1;
                    asm("tanh.approx.f32 %0, %1;" : "=f"(t) : "f"(acc[mi][ni][2] + hp1[cl]));     s1 += t * w0;
                    asm("tanh.approx.f32 %0, %1;" : "=f"(t) : "f"(acc[mi][ni][3] + hp1[cl + 1])); s1 += t * w1;
                }
                sacc[mi][0] += s0;
                sacc[mi][1] += s1;
            }
            __syncthreads();   // epilogue reads done before next tile's wa/hp writes
        }

        float* red = (float*)(smem + OFF_RED);
        #pragma unroll
        for (int mi = 0; mi < 2; mi++) {
            float s0 = sacc[mi][0], s1 = sacc[mi][1];
            s0 += __shfl_xor_sync(0xffffffffu, s0, 1);
            s0 += __shfl_xor_sync(0xffffffffu, s0, 2);
            s1 += __shfl_xor_sync(0xffffffffu, s1, 1);
            s1 += __shfl_xor_sync(0xffffffffu, s1, 2);
            if (tig == 0) {
                int r0 = warp_m * 32 + mi * 16 + g;
                red[warp_n * 128 + r0]     = s0;
                red[warp_n * 128 + r0 + 8] = s1;
            }
        }
        __syncthreads();
        for (int r = tid; r < 128; r += 512)
            score[m0 + r] = (red[r] + red[128 + r]) + (red[256 + r] + red[384 + r]);
        __syncthreads();
    }
}

// ================= GEMM + tanh-dot epilogue (temporal; atomics) ==========
template <int NT>
__global__ __launch_bounds__(512, 1) void gemm_score_mma(
    const __half* __restrict__ A, const __half* __restrict__ W,
    const float* __restrict__ hproj, const float* __restrict__ wa,
    float* __restrict__ score, int K, int rpb)
{
    constexpr int WN = NT / 4;
    constexpr int NI = WN / 8;
    constexpr int STAGE = 16384 + NT * 128;
    constexpr int OFF_WA = 4 * STAGE;
    constexpr int OFF_HP = OFF_WA + NT * 4;

    extern __shared__ char smem[];
    const uint32_t sb = smem_u32(smem);
    const int tid = threadIdx.x;
    const int lane = tid & 31;
    const int warp = tid >> 5;
    const int warp_m = warp >> 2;
    const int warp_n = warp & 3;
    const int m0 = blockIdx.y * 128;
    const int n0 = blockIdx.x * NT;
    const int S = K >> 6;

    {
        float* wa_s = (float*)(smem + OFF_WA);
        float* hp_s = (float*)(smem + OFF_HP);
        for (int i = tid; i < NT; i += 512) wa_s[i] = wa[n0 + i];
        int nb = 128 / rpb; if (nb < 1) nb = 1;
        int b0 = m0 / rpb;
        for (int i = tid; i < nb * NT; i += 512)
            hp_s[i] = hproj[(size_t)(b0 + i / NT) * 1024 + n0 + (i % NT)];
    }

    const __half* Abase = A + (size_t)m0 * K;
    const __half* Wbase = W + (size_t)n0 * K;

    float acc[2][NI][4];
    #pragma unroll
    for (int i = 0; i < 2; i++)
        #pragma unroll
        for (int j = 0; j < NI; j++)
            #pragma unroll
            for (int q = 0; q < 4; q++) acc[i][j][q] = 0.f;

    const int lrow = lane & 15;
    const int lhi  = lane >> 4;
    uint32_t a_off[2], b_off[NI / 2];
    #pragma unroll
    for (int mi = 0; mi < 2; mi++)
        a_off[mi] = tile_off(warp_m * 32 + mi * 16 + lrow, lhi);
    #pragma unroll
    for (int p = 0; p < NI / 2; p++)
        b_off[p] = 16384u + tile_off(warp_n * WN + p * 16 + lrow, lhi);

    LoadCtx<NT> ls;
    ls_init<NT>(ls, K, tid);

    ls_issue<NT>(ls, sb + 0 * STAGE, Abase +   0, Wbase +   0); CP_COMMIT();
    ls_issue<NT>(ls, sb + 1 * STAGE, Abase +  64, Wbase +  64); CP_COMMIT();
    ls_issue<NT>(ls, sb + 2 * STAGE, Abase + 128, Wbase + 128); CP_COMMIT();

    for (int kc = 0; kc < S; kc++) {
        asm volatile("cp.async.wait_group 2;" ::: "memory");
        __syncthreads();
        if (kc + 3 < S)
            ls_issue<NT>(ls, sb + ((kc + 3) & 3) * STAGE,
                         Abase + (kc + 3) * 64, Wbase + (kc + 3) * 64);
        CP_COMMIT();
        const uint32_t stage_base = sb + (kc & 3) * STAGE;
        GEMM_CHUNK(NI, stage_base)
    }

    const float* wa_s = (const float*)(smem + OFF_WA);
    const float* hp_s = (const float*)(smem + OFF_HP);
    const int g = lane >> 2, tig = lane & 3;

    #pragma unroll
    for (int mi = 0; mi < 2; mi++) {
        int r0 = warp_m * 32 + mi * 16 + g;
        int r1 = r0 + 8;
        int bl0 = r0 / rpb, bl1 = r1 / rpb;
        const float* hp0 = hp_s + bl0 * NT;
        const float* hp1 = hp_s + bl1 * NT;
        float s0 = 0.f, s1 = 0.f;
        #pragma unroll
        for (int ni = 0; ni < NI; ni++) {
            int cl = warp_n * WN + ni * 8 + 2 * tig;
            float w0 = wa_s[cl], w1 = wa_s[cl + 1];
            float t;
            asm("tanh.approx.f32 %0, %1;" : "=f"(t) : "f"(acc[mi][ni][0] + hp0[cl]));     s0 += t * w0;
            asm("tanh.approx.f32 %0, %1;" : "=f"(t) : "f"(acc[mi][ni][1] + hp0[cl + 1])); s0 += t * w1;
            asm("tanh.approx.f32 %0, %1;" : "=f"(t) : "f"(acc[mi][ni][2] + hp1[cl]));     s1 += t * w0;
            asm("tanh.approx.f32 %0, %1;" : "=f"(t) : "f"(acc[mi][ni][3] + hp1[cl + 1])); s1 += t * w1;
        }
        s0 += __shfl_xor_sync(0xffffffffu, s0, 1);
        s0 += __shfl_xor_sync(0xffffffffu, s0, 2);
        s1 += __shfl_xor_sync(0xffffffffu, s1, 1);
        s1 += __shfl_xor_sync(0xffffffffu, s1, 2);
        if (tig == 0) {
            atomicAdd(&score[m0 + r0], s0);
            atomicAdd(&score[m0 + r1], s1);
        }
    }
}

// ================= GEMM + bias store (hproj) =================
__global__ __launch_bounds__(512, 1) void gemm_bias_mma(
    const __half* __restrict__ A,
    const __half* __restrict__ Ws, const float* __restrict__ bh_s,
    const float* __restrict__ bv_s, float* __restrict__ out_s,
    const __half* __restrict__ Wt, const float* __restrict__ bh_t,
    const float* __restrict__ bv_t, float* __restrict__ out_t)
{
    constexpr int NT = 256, WN = 64, NI = 8, K = HIDDEN;
    constexpr int STAGE = 16384 + NT * 128;
    constexpr int OFF_B = 4 * STAGE;

    extern __shared__ char smem[];
    const uint32_t sb = smem_u32(smem);
    const int tid = threadIdx.x;
    const int lane = tid & 31;
    const int warp = tid >> 5;
    const int warp_m = warp >> 2;
    const int warp_n = warp & 3;
    const int mat = blockIdx.y >> 2;
    const int n0 = (blockIdx.y & 3) * NT;
    const __half* W = mat ? Wt : Ws;
    const float* bh = mat ? bh_t : bh_s;
    const float* bv = mat ? bv_t : bv_s;
    float* out = mat ? out_t : out_s;

    {
        float* b_s = (float*)(smem + OFF_B);
        for (int i = tid; i < NT; i += 512) b_s[i] = bh[n0 + i] + bv[n0 + i];
    }

    const __half* Abase = A;
    const __half* Wbase = W + (size_t)n0 * K;

    float acc[2][NI][4];
    #pragma unroll
    for (int i = 0; i < 2; i++)
        #pragma unroll
        for (int j = 0; j < NI; j++)
            #pragma unroll
            for (int q = 0; q < 4; q++) acc[i][j][q] = 0.f;

    const int lrow = lane & 15;
    const int lhi  = lane >> 4;
    uint32_t a_off[2], b_off[NI / 2];
    #pragma unroll
    for (int mi = 0; mi < 2; mi++)
        a_off[mi] = tile_off(warp_m * 32 + mi * 16 + lrow, lhi);
    #pragma unroll
    for (int p = 0; p < NI / 2; p++)
        b_off[p] = 16384u + tile_off(warp_n * WN + p * 16 + lrow, lhi);

    LoadCtx<NT> ls;
    ls_init<NT>(ls, K, tid);

    ls_issue<NT>(ls, sb + 0 * STAGE, Abase +   0, Wbase +   0); CP_COMMIT();
    ls_issue<NT>(ls, sb + 1 * STAGE, Abase +  64, Wbase +  64); CP_COMMIT();
    ls_issue<NT>(ls, sb + 2 * STAGE, Abase + 128, Wbase + 128); CP_COMMIT();

    for (int kc = 0; kc < (K >> 6); kc++) {
        asm volatile("cp.async.wait_group 2;" ::: "memory");
        __syncthreads();
        if (kc + 3 < (K >> 6))
            ls_issue<NT>(ls, sb + ((kc + 3) & 3) * STAGE,
                         Abase + (kc + 3) * 64, Wbase + (kc + 3) * 64);
        CP_COMMIT();
        const uint32_t stage_base = sb + (kc & 3) * STAGE;
        GEMM_CHUNK(NI, stage_base)
    }

    const float* b_s = (const float*)(smem + OFF_B);
    const int g = lane >> 2, tig = lane & 3;
    #pragma unroll
    for (int mi = 0; mi < 2; mi++) {
        int r0 = warp_m * 32 + mi * 16 + g;
        int r1 = r0 + 8;
        #pragma unroll
        for (int ni = 0; ni < NI; ni++) {
            int cl = warp_n * WN + ni * 8 + 2 * tig;
            if (r0 < 64) {
                out[r0 * 1024 + n0 + cl]     = acc[mi][ni][0] + b_s[cl];
                out[r0 * 1024 + n0 + cl + 1] = acc[mi][ni][1] + b_s[cl + 1];
            }
            if (r1 < 64) {
                out[r1 * 1024 + n0 + cl]     = acc[mi][ni][2] + b_s[cl];
                out[r1 * 1024 + n0 + cl + 1] = acc[mi][ni][3] + b_s[cl + 1];
            }
        }
    }
}

// ================= small kernels =================
__global__ void zero_kernel(float* __restrict__ p, int n) {
    int i = blockIdx.x * blockDim.x + threadIdx.x;
    if (i < n) p[i] = 0.0f;
}

// f32 -> f16, 8 elements per thread (2x LDG.128 + 1x STG.128), n % 8 == 0
__global__ __launch_bounds__(256) void cvt_f2h8(const float* __restrict__ in,
                                                __half* __restrict__ out, int n) {
    int i = (blockIdx.x * blockDim.x + threadIdx.x) * 8;
    if (i < n) {
        float4 v0 = *(const float4*)(in + i);
        float4 v1 = *(const float4*)(in + i + 4);
        uint4 o;
        o.x = h2_bits(__floats2half2_rn(v0.x, v0.y));
        o.y = h2_bits(__floats2half2_rn(v0.z, v0.w));
        o.z = h2_bits(__floats2half2_rn(v1.x, v1.y));
        o.w = h2_bits(__floats2half2_rn(v1.z, v1.w));
        *(uint4*)(out + i) = o;
    }
}

// hidden [64,1024] f32 -> [128,1024] f16 (rows 64..127 zero)
__global__ __launch_bounds__(256) void cvt_hid_pad(const float* __restrict__ in,
                                                   __half* __restrict__ out) {
    int i = (blockIdx.x * blockDim.x + threadIdx.x) * 4;
    if (i < 128 * HIDDEN) {
        __half2* o = (__half2*)(out + i);
        if (i < 64 * HIDDEN) {
            float4 v = *(const float4*)(in + i);
            o[0] = __floats2half2_rn(v.x, v.y);
            o[1] = __floats2half2_rn(v.z, v.w);
        } else {
            o[0] = __floats2half2_rn(0.f, 0.f);
            o[1] = __floats2half2_rn(0.f, 0.f);
        }
    }
}

// spatial softmax + weighted object sum + concat (fp32 + fp16 outputs)
__global__ __launch_bounds__(256) void spatial_kernel(
    const __half* __restrict__ obj_h, const float* __restrict__ frame,
    const float* __restrict__ score, float* __restrict__ feat,
    __half* __restrict__ feat_h)
{
    int bf = blockIdx.x;
    __shared__ float alpha[NN];
    if (threadIdx.x == 0) {
        float s[NN];
        float mx = -1e30f;
        #pragma unroll
        for (int n = 0; n < NN; n++) { s[n] = score[bf * NN + n]; mx = fmaxf(mx, s[n]); }
        float sum = 0.f;
        #pragma unroll
        for (int n = 0; n < NN; n++) { float e = expf(s[n] - mx); alpha[n] = e; sum += e; }
        float inv = 1.f / sum;
        #pragma unroll
        for (int n = 0; n < NN; n++) alpha[n] *= inv;
    }
    __syncthreads();

    const uint4* base4 = (const uint4*)(obj_h + (size_t)bf * NN * REGION);
    float* frow = feat + (size_t)bf * FEAT2;
    uint4* hrow4 = (uint4*)(feat_h + (size_t)bf * FEAT2);
    for (int d8 = threadIdx.x; d8 < REGION / 8; d8 += 256) {
        float a[8] = {0, 0, 0, 0, 0, 0, 0, 0};
        #pragma unroll 4
        for (int n = 0; n < NN; n++) {
            uint4 v = base4[n * (REGION / 8) + d8];
            float al = alpha[n];
            float2 p0 = __half22float2(*(__half2*)&v.x);
            float2 p1 = __half22float2(*(__half2*)&v.y);
            float2 p2 = __half22float2(*(__half2*)&v.z);
            float2 p3 = __half22float2(*(__half2*)&v.w);
            a[0] += al * p0.x; a[1] += al * p0.y;
            a[2] += al * p1.x; a[3] += al * p1.y;
            a[4] += al * p2.x; a[5] += al * p2.y;
            a[6] += al * p3.x; a[7] += al * p3.y;
        }
        #pragma unroll
        for (int q = 0; q < 8; q++) frow[d8 * 8 + q] = a[q];
        uint4 o;
        o.x = h2_bits(__floats2half2_rn(a[0], a[1]));
        o.y = h2_bits(__floats2half2_rn(a[2], a[3]));
        o.z = h2_bits(__floats2half2_rn(a[4], a[5]));
        o.w = h2_bits(__floats2half2_rn(a[6], a[7]));
        hrow4[d8] = o;
    }
    const float* frm = frame + (size_t)bf * (2 * HIDDEN);
    for (int d = threadIdx.x; d < 2 * HIDDEN; d += 256) {
        float v = frm[d];
        frow[REGION + d] = v;
        feat_h[(size_t)bf * FEAT2 + REGION + d] = __float2half_rn(v);
    }
}

// temporal softmax + weighted sum, fp32 feat -> fp32 output
__global__ __launch_bounds__(256) void temporal_kernel(
    const float* __restrict__ feat, const float* __restrict__ score2,
    float* __restrict__ out)
{
    int b = blockIdx.x;
    __shared__ float beta[FF];
    if (threadIdx.x == 0) {
        float s[FF];
        float mx = -1e30f;
        #pragma unroll
        for (int f = 0; f < FF; f++) { s[f] = score2[b * FF + f]; mx = fmaxf(mx, s[f]); }
        float sum = 0.f;
        #pragma unroll
        for (int f = 0; f < FF; f++) { float e = expf(s[f] - mx); beta[f] = e; sum += e; }
        float inv = 1.f / sum;
        #pragma unroll
        for (int f = 0; f < FF; f++) beta[f] *= inv;
    }
    __syncthreads();

    int d0 = blockIdx.y * (FEAT2 / 4);
    for (int d = d0 + threadIdx.x; d < d0 + FEAT2 / 4; d += 256) {
        float acc = 0.f;
        #pragma unroll 8
        for (int f = 0; f < FF; f++)
            acc += beta[f] * feat[((size_t)b * FF + f) * FEAT2 + d];
        out[(size_t)b * FEAT2 + d] = acc;
    }
}

// ================= launch =================
extern "C" void kernel_launch(void* const* d_in, const int* in_sizes, int n_in,
                              void* d_out, int out_size)
{
    const float* frame  = (const float*)d_in[0];
    const float* obj    = (const float*)d_in[1];
    const float* hidden = (const float*)d_in[2];
    const float* s_wh_w = (const float*)d_in[3];
    const float* s_wh_b = (const float*)d_in[4];
    const float* s_wv_w = (const float*)d_in[5];
    const float* s_wv_b = (const float*)d_in[6];
    const float* s_wa_w = (const float*)d_in[7];
    const float* t_wh_w = (const float*)d_in[8];
    const float* t_wh_b = (const float*)d_in[9];
    const float* t_wv_w = (const float*)d_in[10];
    const float* t_wv_b = (const float*)d_in[11];
    const float* t_wa_w = (const float*)d_in[12];
    float* out = (float*)d_out;

    float *p_hs, *p_ht, *p_s1, *p_feat, *p_s2;
    __half *p_obj_h, *p_feat_h, *p_swv_h, *p_twv_h, *p_swh_h, *p_twh_h, *p_hid_h;
    cudaGetSymbolAddress((void**)&p_hs, g_hproj_s);
    cudaGetSymbolAddress((void**)&p_ht, g_hproj_t);
    cudaGetSymbolAddress((void**)&p_s1, g_score1);
    cudaGetSymbolAddress((void**)&p_feat, g_feat);
    cudaGetSymbolAddress((void**)&p_s2, g_score2);
    cudaGetSymbolAddress((void**)&p_obj_h, g_obj_h);
    cudaGetSymbolAddress((void**)&p_feat_h, g_feat_h);
    cudaGetSymbolAddress((void**)&p_swv_h, g_swv_h);
    cudaGetSymbolAddress((void**)&p_twv_h, g_twv_h);
    cudaGetSymbolAddress((void**)&p_swh_h, g_swh_h);
    cudaGetSymbolAddress((void**)&p_twh_h, g_twh_h);
    cudaGetSymbolAddress((void**)&p_hid_h, g_hid_h);

    const int SMEM_PERS = 4 * (16384 + 256 * 128) + 256 * 4 + 4 * 256 * 4 + 4 * 128 * 4; // 203776
    const int SMEM_128  = 4 * (16384 + 128 * 128) + 128 * 4 + 4 * 128 * 4;               // 133632
    const int SMEM_B    = 4 * (16384 + 256 * 128) + 256 * 4;                             // 197632
    cudaFuncSetAttribute(gemm_score_pers<256, 4>, cudaFuncAttributeMaxDynamicSharedMemorySize, SMEM_PERS);
    cudaFuncSetAttribute(gemm_score_mma<128>, cudaFuncAttributeMaxDynamicSharedMemorySize, SMEM_128);
    cudaFuncSetAttribute(gemm_bias_mma, cudaFuncAttributeMaxDynamicSharedMemorySize, SMEM_B);

    // fp16 conversions (8 elems/thread)
    {
        int n_swh = 1024 * HIDDEN;
        cvt_f2h8<<<(n_swh / 8 + 255) / 256, 256>>>(s_wh_w, p_swh_h, n_swh);
        cvt_f2h8<<<(n_swh / 8 + 255) / 256, 256>>>(t_wh_w, p_twh_h, n_swh);
        cvt_hid_pad<<<(128 * HIDDEN / 4 + 255) / 256, 256>>>(hidden, p_hid_h);
        int n_swv = 1024 * REGION;
        cvt_f2h8<<<(n_swv / 8 + 255) / 256, 256>>>(s_wv_w, p_swv_h, n_swv);
        int n_twv = 1024 * FEAT2;
        cvt_f2h8<<<(n_twv / 8 + 255) / 256, 256>>>(t_wv_w, p_twv_h, n_twv);
        int n_obj = M1 * REGION;
        cvt_f2h8<<<(n_obj / 8 + 255) / 256, 256>>>(obj, p_obj_h, n_obj);
    }

    // hidden-state projections as one mma GEMM launch (both matrices)
    gemm_bias_mma<<<dim3(1, 8), 512, SMEM_B>>>(p_hid_h,
                                               p_swh_h, s_wh_b, s_wv_b, p_hs,
                                               p_twh_h, t_wh_b, t_wv_b, p_ht);

    // spatial attention scores: persistent GEMM, 144 CTAs x 4 m-blocks x 4 n-tiles
    gemm_score_pers<256, 4><<<144, 512, SMEM_PERS>>>(
        p_obj_h, p_swv_h, p_hs, s_wa_w, p_s1, REGION, FF * NN, (M1 / 128) / 144);

    // softmax over boxes + weighted object sum + concat (fp32 + fp16 feat)
    spatial_kernel<<<M2, 256>>>(p_obj_h, frame, p_s1, p_feat, p_feat_h);

    // temporal attention scores
    zero_kernel<<<(M2 + 255) / 256, 256>>>(p_s2, M2);
    gemm_score_mma<128><<<dim3(8, M2 / 128), 512, SMEM_128>>>(
        p_feat_h, p_twv_h, p_ht, t_wa_w, p_s2, FEAT2, FF);

    // softmax over frames + weighted feat sum (fp32) -> [64, 3072]
    temporal_kernel<<<dim3(BB, 4), 256>>>(p_feat, p_s2, out);
}